// round 7
// baseline (speedup 1.0000x reference)
#include <cuda_runtime.h>
#include <math.h>

#define Bsz 32
#define Ssz 512
#define Hsz 1024
#define Osz 1024
#define GRID 148

typedef unsigned long long ull;

// ---------------- device scratch ----------------
__device__ float g_xp0[(size_t)Ssz * Bsz * 3 * Hsz];   // layer0 x-projections (s,b,3H)
__device__ float g_h1all[(size_t)Ssz * Bsz * Hsz];     // all layer1 hidden states (s,b,H)
__device__ float g_h0[Bsz * Hsz];
__device__ float g_h1[Bsz * Hsz];
__device__ float g_z0[Bsz * Hsz];
__device__ float g_rh0[Bsz * Hsz];
__device__ float g_z1[Bsz * Hsz];
__device__ float g_rh1[Bsz * Hsz];
__device__ float g_gc1[Bsz * Hsz];
__device__ float g_pz1[Bsz * Hsz];           // raw h1 @ Wh[1][0]^T
__device__ float g_pr1[Bsz * Hsz];           // raw h1 @ Wh[1][1]^T
__device__ unsigned g_barcnt;

__device__ __forceinline__ float sigf(float x) { return 1.f / (1.f + expf(-x)); }

// ---------------- packed fp32x2 FMA (Blackwell) ----------------
__device__ __forceinline__ void fma2(ull& c, ull a, ull b) {
    asm("fma.rn.f32x2 %0, %1, %2, %0;" : "+l"(c) : "l"(a), "l"(b));
}
__device__ __forceinline__ ull pk2(float lo, float hi) {
    ull r; asm("mov.b64 %0, {%1, %2};" : "=l"(r) : "f"(lo), "f"(hi)); return r;
}
__device__ __forceinline__ void upk2(ull v, float& lo, float& hi) {
    asm("mov.b64 {%0, %1}, %2;" : "=f"(lo), "=f"(hi) : "l"(v));
}

// 4x4 micro-tile step: a = 4 m-values, b = 4 n-values
#define FMA2_STEP() do { \
    ull b01 = pk2(b.x, b.y), b23 = pk2(b.z, b.w); \
    ull am; \
    am = pk2(a.x, a.x); fma2(acc2[0][0], am, b01); fma2(acc2[0][1], am, b23); \
    am = pk2(a.y, a.y); fma2(acc2[1][0], am, b01); fma2(acc2[1][1], am, b23); \
    am = pk2(a.z, a.z); fma2(acc2[2][0], am, b01); fma2(acc2[2][1], am, b23); \
    am = pk2(a.w, a.w); fma2(acc2[3][0], am, b01); fma2(acc2[3][1], am, b23); \
} while (0)

// ---------------- grid barrier (monotonic counter, reset in k_init) ----------------
__device__ __forceinline__ void gridbar(unsigned gen) {
    __syncthreads();
    if (threadIdx.x == 0) {
        __threadfence();
        atomicAdd(&g_barcnt, 1u);
        const unsigned tgt = gen * GRID;
        while (*(volatile unsigned*)&g_barcnt < tgt) { }
        __threadfence();
    }
    __syncthreads();
}

// ---------------- init ----------------
__global__ void k_init(const float* __restrict__ h0in) {
    if (blockIdx.x == 0 && threadIdx.x == 0) g_barcnt = 0u;
    int idx = blockIdx.x * blockDim.x + threadIdx.x;
    int b = idx >> 11;
    int r = idx & 2047;
    int l = r >> 10;
    int i = r & 1023;
    float v = h0in[idx];
    if (l == 0) g_h0[b * Hsz + i] = v;
    else        g_h1[b * Hsz + i] = v;
}

// ---------------- big GEMM: xp0 = x @ Wx[0]^T + bx[0] ----------------
// M=16384 (s*32+b), N=3072, K=1024. 64x64 tile, 256 thr, 4x4 micro, prefetch.
__global__ __launch_bounds__(256) void k_xproj(const float* __restrict__ x,
                                               const float* __restrict__ Wx,
                                               const float* __restrict__ bxp) {
    __shared__ __align__(16) float sm[2048];
    float* As = sm;
    float* Bs = sm + 1024;
    const int tid = threadIdx.x;
    const int bm = blockIdx.y << 6;
    const int bn = blockIdx.x << 6;
    const int lr = tid >> 2;
    const int lk = (tid & 3) << 2;
    const int mrow = bm + lr;
    const size_t a_off = ((size_t)(mrow & 31) * Ssz + (mrow >> 5)) * Hsz;
    const size_t b_off = (size_t)(bn + lr) * Hsz;
    const int tm = (tid >> 4) << 2;
    const int tn = (tid & 15) << 2;
    ull acc2[4][2] = {};
    float4 av = *(const float4*)(x + a_off + lk);
    float4 bv = *(const float4*)(Wx + b_off + lk);
    for (int k0 = 0; k0 < Hsz; k0 += 16) {
        As[(lk + 0) * 64 + lr] = av.x; As[(lk + 1) * 64 + lr] = av.y;
        As[(lk + 2) * 64 + lr] = av.z; As[(lk + 3) * 64 + lr] = av.w;
        Bs[(lk + 0) * 64 + lr] = bv.x; Bs[(lk + 1) * 64 + lr] = bv.y;
        Bs[(lk + 2) * 64 + lr] = bv.z; Bs[(lk + 3) * 64 + lr] = bv.w;
        __syncthreads();
        if (k0 + 16 < Hsz) {
            av = *(const float4*)(x + a_off + k0 + 16 + lk);
            bv = *(const float4*)(Wx + b_off + k0 + 16 + lk);
        }
#pragma unroll
        for (int kk = 0; kk < 16; kk++) {
            float4 a = *(const float4*)(As + kk * 64 + tm);
            float4 b = *(const float4*)(Bs + kk * 64 + tn);
            FMA2_STEP();
        }
        __syncthreads();
    }
#pragma unroll
    for (int i = 0; i < 4; i++) {
        size_t ro = (size_t)(bm + tm + i) * 3072;
        float v0, v1, v2, v3;
        upk2(acc2[i][0], v0, v1);
        upk2(acc2[i][1], v2, v3);
        int n = bn + tn;
        g_xp0[ro + n + 0] = v0 + bxp[n + 0];
        g_xp0[ro + n + 1] = v1 + bxp[n + 1];
        g_xp0[ro + n + 2] = v2 + bxp[n + 2];
        g_xp0[ro + n + 3] = v3 + bxp[n + 3];
    }
}

// ---------------- big GEMM: out = h1all @ Wo^T + bo ----------------
__global__ __launch_bounds__(256) void k_out(const float* __restrict__ Wo,
                                             const float* __restrict__ bo,
                                             float* __restrict__ out) {
    __shared__ __align__(16) float sm[2048];
    float* As = sm;
    float* Bs = sm + 1024;
    const int tid = threadIdx.x;
    const int bm = blockIdx.y << 6;
    const int bn = blockIdx.x << 6;
    const int lr = tid >> 2;
    const int lk = (tid & 3) << 2;
    const size_t a_off = (size_t)(bm + lr) * Hsz;
    const size_t b_off = (size_t)(bn + lr) * Hsz;
    const int tm = (tid >> 4) << 2;
    const int tn = (tid & 15) << 2;
    ull acc2[4][2] = {};
    float4 av = *(const float4*)(g_h1all + a_off + lk);
    float4 bv = *(const float4*)(Wo + b_off + lk);
    for (int k0 = 0; k0 < Hsz; k0 += 16) {
        As[(lk + 0) * 64 + lr] = av.x; As[(lk + 1) * 64 + lr] = av.y;
        As[(lk + 2) * 64 + lr] = av.z; As[(lk + 3) * 64 + lr] = av.w;
        Bs[(lk + 0) * 64 + lr] = bv.x; Bs[(lk + 1) * 64 + lr] = bv.y;
        Bs[(lk + 2) * 64 + lr] = bv.z; Bs[(lk + 3) * 64 + lr] = bv.w;
        __syncthreads();
        if (k0 + 16 < Hsz) {
            av = *(const float4*)(g_h1all + a_off + k0 + 16 + lk);
            bv = *(const float4*)(Wo + b_off + k0 + 16 + lk);
        }
#pragma unroll
        for (int kk = 0; kk < 16; kk++) {
            float4 a = *(const float4*)(As + kk * 64 + tm);
            float4 b = *(const float4*)(Bs + kk * 64 + tn);
            FMA2_STEP();
        }
        __syncthreads();
    }
#pragma unroll
    for (int i = 0; i < 4; i++) {
        int m = bm + tm + i;
        int bb = m & 31;
        int s = m >> 5;
        size_t ro = ((size_t)bb * Ssz + s) * Osz;
        float v0, v1, v2, v3;
        upk2(acc2[i][0], v0, v1);
        upk2(acc2[i][1], v2, v3);
        int n = bn + tn;
        out[ro + n + 0] = v0 + bo[n + 0];
        out[ro + n + 1] = v1 + bo[n + 1];
        out[ro + n + 2] = v2 + bo[n + 2];
        out[ro + n + 3] = v3 + bo[n + 3];
    }
}

// ---------------- 32x32 tile GEMM (in-block 4-way K-split, prefetched) ----------------
__device__ __forceinline__ void ldg_chunk(const float* __restrict__ Ap,
                                          const float* __restrict__ Wb,
                                          int n0, int kk0, int u,
                                          float4 av[2], float4 wv[2]) {
#pragma unroll
    for (int r = 0; r < 2; r++) {
        int p = u + (r << 6);
        int mr = p >> 2;
        int kq = (p & 3) << 2;
        av[r] = *(const float4*)(Ap + mr * Hsz + kk0 + kq);
        wv[r] = *(const float4*)(Wb + (size_t)(n0 + mr) * Hsz + kk0 + kq);
    }
}

__device__ __forceinline__ void sts_chunk(const float4 av[2], const float4 wv[2],
                                          int u, float* As, float* Bs) {
#pragma unroll
    for (int r = 0; r < 2; r++) {
        int p = u + (r << 6);
        int mr = p >> 2;
        int kq = (p & 3) << 2;
        As[(kq + 0) * 32 + mr] = av[r].x; As[(kq + 1) * 32 + mr] = av[r].y;
        As[(kq + 2) * 32 + mr] = av[r].z; As[(kq + 3) * 32 + mr] = av[r].w;
        Bs[(kq + 0) * 32 + mr] = wv[r].x; Bs[(kq + 1) * 32 + mr] = wv[r].y;
        Bs[(kq + 2) * 32 + mr] = wv[r].z; Bs[(kq + 3) * 32 + mr] = wv[r].w;
    }
}

// 32x32 tile of Ap(32xK) @ W(rows n0.., stride Hsz)^T over K=[0,1024).
// Group-partial results land in sm[g*1024 + m*32 + n]; caller sums 4 groups.
__device__ __forceinline__ void tile_accum(const float* __restrict__ Ap,
                                           const float* __restrict__ Wb,
                                           int n0, int g, int u, int tm, int tn,
                                           float* As, float* Bs, float* sm) {
    ull acc2[4][2] = {};
    const int kb = g << 8;               // 256-wide K slice per group
    float4 a0[2], w0[2], a1[2], w1[2];
    ldg_chunk(Ap, Wb, n0, kb, u, a0, w0);
    for (int kc = 0; kc < 256; kc += 16) {
        sts_chunk(a0, w0, u, As, Bs);
        __syncthreads();
        if (kc + 16 < 256) ldg_chunk(Ap, Wb, n0, kb + kc + 16, u, a1, w1);
#pragma unroll
        for (int kk = 0; kk < 16; kk++) {
            float4 a = *(const float4*)(As + kk * 32 + tm);
            float4 b = *(const float4*)(Bs + kk * 32 + tn);
            FMA2_STEP();
        }
        __syncthreads();
#pragma unroll
        for (int r = 0; r < 2; r++) { a0[r] = a1[r]; w0[r] = w1[r]; }
    }
#pragma unroll
    for (int i = 0; i < 4; i++) {
        float v0, v1, v2, v3;
        upk2(acc2[i][0], v0, v1);
        upk2(acc2[i][1], v2, v3);
        float* d = sm + (g << 10) + (tm + i) * 32 + tn;
        d[0] = v0; d[1] = v1; d[2] = v2; d[3] = v3;
    }
    __syncthreads();
}

#define SM4(m, n) (sm[(m)*32+(n)] + sm[1024+(m)*32+(n)] + sm[2048+(m)*32+(n)] + sm[3072+(m)*32+(n)])

// ---------------- persistent recurrence kernel ----------------
__global__ __launch_bounds__(256, 1) void k_recur(const float* __restrict__ Wx,
                                                  const float* __restrict__ Wh,
                                                  const float* __restrict__ bxp) {
    __shared__ __align__(16) float sm[4096];
    const int tid = threadIdx.x;
    const int b = blockIdx.x;
    const int g = tid >> 6;
    const int u = tid & 63;
    float* As = sm + (g << 10);
    float* Bs = As + 512;
    const int tm = (u >> 3) << 2;
    const int tn = (u & 7) << 2;
    unsigned bar = 0;

    for (int t = 0; t < Ssz; t++) {
        const float* xp = g_xp0 + (size_t)t * Bsz * 3072;

        // ---- Phase A: L0 z,r gates + L1 raw Wh z,r projections (128 tasks) ----
        if (b < 128) {
            const int sel = b >> 5;            // 0:z0 1:r0 2:pz1 3:pr1
            const int n0 = (b & 31) << 5;
            const float* Ap = (sel < 2) ? g_h0 : g_h1;
            const int widx = (sel == 0) ? 0 : (sel == 1) ? 1 : (sel == 2) ? 3 : 4;
            tile_accum(Ap, Wh + (size_t)widx * 1048576, n0, g, u, tm, tn, As, Bs, sm);
#pragma unroll
            for (int jj = 0; jj < 4; jj++) {
                int o = tid + (jj << 8);
                int m = o >> 5, n = o & 31;
                float v = SM4(m, n);
                int i = n0 + n;
                if (sel == 0)      g_z0[m * Hsz + i] = sigf(v + xp[m * 3072 + i]);
                else if (sel == 1) g_rh0[m * Hsz + i] = sigf(v + xp[m * 3072 + 1024 + i]) * g_h0[m * Hsz + i];
                else if (sel == 2) g_pz1[m * Hsz + i] = v;
                else               g_pr1[m * Hsz + i] = v;
            }
        }
        gridbar(++bar);

        // ---- Phase B: L0 candidate GEMM (32 tasks, full K) + fused h0 update ----
        if (b < 32) {
            const int n0 = b << 5;
            tile_accum(g_rh0, Wh + (size_t)2 * 1048576, n0, g, u, tm, tn, As, Bs, sm);
#pragma unroll
            for (int jj = 0; jj < 4; jj++) {
                int o = tid + (jj << 8);
                int m = o >> 5, n = o & 31;
                float v = SM4(m, n);
                int i = n0 + n;
                float c = tanhf(v + xp[m * 3072 + 2048 + i]);
                float z = g_z0[m * Hsz + i];
                float h = g_h0[m * Hsz + i];
                g_h0[m * Hsz + i] = z * h + (1.f - z) * c;
            }
        }
        gridbar(++bar);

        // ---- Phase C: L1 x-projections + gate fuse (96 tasks) ----
        if (b < 96) {
            const int gate = b >> 5;
            const int n0 = (b & 31) << 5;
            tile_accum(g_h0, Wx + (size_t)(3 + gate) * 1048576, n0, g, u, tm, tn, As, Bs, sm);
#pragma unroll
            for (int jj = 0; jj < 4; jj++) {
                int o = tid + (jj << 8);
                int m = o >> 5, n = o & 31;
                float v = SM4(m, n);
                int i = n0 + n;
                float val = v + bxp[3072 + (gate << 10) + i];
                if (gate == 0)      g_z1[m * Hsz + i] = sigf(val + g_pz1[m * Hsz + i]);
                else if (gate == 1) g_rh1[m * Hsz + i] = sigf(val + g_pr1[m * Hsz + i]) * g_h1[m * Hsz + i];
                else                g_gc1[m * Hsz + i] = val;
            }
        }
        gridbar(++bar);

        // ---- Phase D: L1 candidate GEMM (32 tasks) + fused h1 update + store ----
        if (b < 32) {
            const int n0 = b << 5;
            tile_accum(g_rh1, Wh + (size_t)5 * 1048576, n0, g, u, tm, tn, As, Bs, sm);
#pragma unroll
            for (int jj = 0; jj < 4; jj++) {
                int o = tid + (jj << 8);
                int m = o >> 5, n = o & 31;
                float v = SM4(m, n);
                int i = n0 + n;
                float c = tanhf(v + g_gc1[m * Hsz + i]);
                float z = g_z1[m * Hsz + i];
                float h = g_h1[m * Hsz + i];
                float hn = z * h + (1.f - z) * c;
                g_h1[m * Hsz + i] = hn;
                g_h1all[(size_t)t * Bsz * Hsz + m * Hsz + i] = hn;
            }
        }
        gridbar(++bar);
    }
}

// ---- final hidden state (B,L,H) appended after layer_output ----
__global__ void k_hid(float* __restrict__ out) {
    int idx = blockIdx.x * blockDim.x + threadIdx.x;
    int b = idx >> 11;
    int r = idx & 2047;
    int l = r >> 10;
    int i = r & 1023;
    out[(size_t)Bsz * Ssz * Osz + idx] = (l == 0 ? g_h0 : g_h1)[b * Hsz + i];
}

// ---------------- launch (5 graph nodes) ----------------
extern "C" void kernel_launch(void* const* d_in, const int* in_sizes, int n_in,
                              void* d_out, int out_size) {
    const float* x   = (const float*)d_in[0];
    const float* h0  = (const float*)d_in[1];
    const float* Wx  = (const float*)d_in[2];
    const float* Wh  = (const float*)d_in[3];
    const float* bx  = (const float*)d_in[4];
    const float* Wo  = (const float*)d_in[5];
    const float* bo  = (const float*)d_in[6];
    float* out = (float*)d_out;

    k_init<<<64, 1024>>>(h0);
    k_xproj<<<dim3(48, 256), 256>>>(x, Wx, bx);
    k_recur<<<GRID, 256>>>(Wx, Wh, bx);
    k_out<<<dim3(16, 256), 256>>>(Wo, bo, out);
    k_hid<<<64, 1024>>>(out);
}

// round 8
// speedup vs baseline: 1.3596x; 1.3596x over previous
#include <cuda_runtime.h>
#include <math.h>

#define Bsz 32
#define Ssz 512
#define Hsz 1024
#define Osz 1024
#define GRID 148

// ---------------- device scratch ----------------
__device__ float g_xp0[(size_t)Ssz * Bsz * 3 * Hsz];   // layer0 x-projections (s,b,3H)
__device__ float g_h1all[(size_t)Ssz * Bsz * Hsz];     // all layer1 hidden states (s,b,H)
__device__ float g_h0[Bsz * Hsz];
__device__ float g_h1[Bsz * Hsz];
__device__ float g_z0[Bsz * Hsz];
__device__ float g_rh0[Bsz * Hsz];
__device__ float g_z1[Bsz * Hsz];
__device__ float g_rh1[Bsz * Hsz];
__device__ float g_gc1[Bsz * Hsz];
__device__ float g_pz1[Bsz * Hsz];           // raw h1 @ Wh[1][0]^T
__device__ float g_pr1[Bsz * Hsz];           // raw h1 @ Wh[1][1]^T
__device__ float g_partB[4 * Bsz * Hsz];     // K-split partials, layer0 candidate
__device__ float g_partD[4 * Bsz * Hsz];     // K-split partials, layer1 candidate
__device__ unsigned g_tickB[32];             // per-tile tickets (monotonic)
__device__ unsigned g_tickD[32];
__device__ unsigned g_barcnt;

__device__ __forceinline__ float sigf(float x) { return 1.f / (1.f + expf(-x)); }

#define FMA16() do { \
    acc[0][0] += a.x*b.x; acc[0][1] += a.x*b.y; acc[0][2] += a.x*b.z; acc[0][3] += a.x*b.w; \
    acc[1][0] += a.y*b.x; acc[1][1] += a.y*b.y; acc[1][2] += a.y*b.z; acc[1][3] += a.y*b.w; \
    acc[2][0] += a.z*b.x; acc[2][1] += a.z*b.y; acc[2][2] += a.z*b.z; acc[2][3] += a.z*b.w; \
    acc[3][0] += a.w*b.x; acc[3][1] += a.w*b.y; acc[3][2] += a.w*b.z; acc[3][3] += a.w*b.w; \
} while (0)

// ---------------- grid barrier (monotonic counter) ----------------
__device__ __forceinline__ void gridbar(unsigned gen) {
    __syncthreads();
    __threadfence();                       // all threads: publish my stores
    if (threadIdx.x == 0) {
        atomicAdd(&g_barcnt, 1u);
        const unsigned tgt = gen * GRID;
        while (*(volatile unsigned*)&g_barcnt < tgt) { }
    }
    __syncthreads();
    __threadfence();                       // all threads: invalidate L1 before consuming
}

// ---------------- init ----------------
__global__ void k_init(const float* __restrict__ h0in) {
    if (blockIdx.x == 0 && threadIdx.x == 0) g_barcnt = 0u;
    int idx = blockIdx.x * blockDim.x + threadIdx.x;
    int b = idx >> 11;
    int r = idx & 2047;
    int l = r >> 10;
    int i = r & 1023;
    float v = h0in[idx];
    if (l == 0) g_h0[b * Hsz + i] = v;
    else        g_h1[b * Hsz + i] = v;
}

// ---------------- big GEMM: xp0 = x @ Wx[0]^T + bx[0] (scalar FMA) ----------------
__global__ __launch_bounds__(256) void k_xproj(const float* __restrict__ x,
                                               const float* __restrict__ Wx,
                                               const float* __restrict__ bxp) {
    __shared__ __align__(16) float sm[2048];
    float* As = sm;
    float* Bs = sm + 1024;
    const int tid = threadIdx.x;
    const int bm = blockIdx.y << 6;
    const int bn = blockIdx.x << 6;
    const int lr = tid >> 2;
    const int lk = (tid & 3) << 2;
    const int mrow = bm + lr;
    const size_t a_off = ((size_t)(mrow & 31) * Ssz + (mrow >> 5)) * Hsz;
    const size_t b_off = (size_t)(bn + lr) * Hsz;
    const int tm = (tid >> 4) << 2;
    const int tn = (tid & 15) << 2;
    float acc[4][4] = {};
    float4 av = *(const float4*)(x + a_off + lk);
    float4 bv = *(const float4*)(Wx + b_off + lk);
    for (int k0 = 0; k0 < Hsz; k0 += 16) {
        As[(lk + 0) * 64 + lr] = av.x; As[(lk + 1) * 64 + lr] = av.y;
        As[(lk + 2) * 64 + lr] = av.z; As[(lk + 3) * 64 + lr] = av.w;
        Bs[(lk + 0) * 64 + lr] = bv.x; Bs[(lk + 1) * 64 + lr] = bv.y;
        Bs[(lk + 2) * 64 + lr] = bv.z; Bs[(lk + 3) * 64 + lr] = bv.w;
        __syncthreads();
        if (k0 + 16 < Hsz) {
            av = *(const float4*)(x + a_off + k0 + 16 + lk);
            bv = *(const float4*)(Wx + b_off + k0 + 16 + lk);
        }
#pragma unroll
        for (int kk = 0; kk < 16; kk++) {
            float4 a = *(const float4*)(As + kk * 64 + tm);
            float4 b = *(const float4*)(Bs + kk * 64 + tn);
            FMA16();
        }
        __syncthreads();
    }
#pragma unroll
    for (int i = 0; i < 4; i++) {
        size_t ro = (size_t)(bm + tm + i) * 3072;
#pragma unroll
        for (int j = 0; j < 4; j++) {
            int n = bn + tn + j;
            g_xp0[ro + n] = acc[i][j] + bxp[n];
        }
    }
}

// ---------------- big GEMM: out = h1all @ Wo^T + bo (scalar FMA) ----------------
__global__ __launch_bounds__(256) void k_out(const float* __restrict__ Wo,
                                             const float* __restrict__ bo,
                                             float* __restrict__ out) {
    __shared__ __align__(16) float sm[2048];
    float* As = sm;
    float* Bs = sm + 1024;
    const int tid = threadIdx.x;
    const int bm = blockIdx.y << 6;
    const int bn = blockIdx.x << 6;
    const int lr = tid >> 2;
    const int lk = (tid & 3) << 2;
    const size_t a_off = (size_t)(bm + lr) * Hsz;
    const size_t b_off = (size_t)(bn + lr) * Hsz;
    const int tm = (tid >> 4) << 2;
    const int tn = (tid & 15) << 2;
    float acc[4][4] = {};
    float4 av = *(const float4*)(g_h1all + a_off + lk);
    float4 bv = *(const float4*)(Wo + b_off + lk);
    for (int k0 = 0; k0 < Hsz; k0 += 16) {
        As[(lk + 0) * 64 + lr] = av.x; As[(lk + 1) * 64 + lr] = av.y;
        As[(lk + 2) * 64 + lr] = av.z; As[(lk + 3) * 64 + lr] = av.w;
        Bs[(lk + 0) * 64 + lr] = bv.x; Bs[(lk + 1) * 64 + lr] = bv.y;
        Bs[(lk + 2) * 64 + lr] = bv.z; Bs[(lk + 3) * 64 + lr] = bv.w;
        __syncthreads();
        if (k0 + 16 < Hsz) {
            av = *(const float4*)(g_h1all + a_off + k0 + 16 + lk);
            bv = *(const float4*)(Wo + b_off + k0 + 16 + lk);
        }
#pragma unroll
        for (int kk = 0; kk < 16; kk++) {
            float4 a = *(const float4*)(As + kk * 64 + tm);
            float4 b = *(const float4*)(Bs + kk * 64 + tn);
            FMA16();
        }
        __syncthreads();
    }
#pragma unroll
    for (int i = 0; i < 4; i++) {
        int m = bm + tm + i;
        int bb = m & 31;
        int s = m >> 5;
        size_t ro = ((size_t)bb * Ssz + s) * Osz;
#pragma unroll
        for (int j = 0; j < 4; j++) {
            int n = bn + tn + j;
            out[ro + n] = acc[i][j] + bo[n];
        }
    }
}

// ---------------- 32x32 tile GEMM (in-block 4-way K-split, prefetched) ----------------
__device__ __forceinline__ void ldg_chunk(const float* __restrict__ Ap,
                                          const float* __restrict__ Wb,
                                          int n0, int kk0, int u,
                                          float4 av[2], float4 wv[2]) {
#pragma unroll
    for (int r = 0; r < 2; r++) {
        int p = u + (r << 6);
        int mr = p >> 2;
        int kq = (p & 3) << 2;
        av[r] = *(const float4*)(Ap + mr * Hsz + kk0 + kq);
        wv[r] = *(const float4*)(Wb + (size_t)(n0 + mr) * Hsz + kk0 + kq);
    }
}

__device__ __forceinline__ void sts_chunk(const float4 av[2], const float4 wv[2],
                                          int u, float* As, float* Bs) {
#pragma unroll
    for (int r = 0; r < 2; r++) {
        int p = u + (r << 6);
        int mr = p >> 2;
        int kq = (p & 3) << 2;
        As[(kq + 0) * 32 + mr] = av[r].x; As[(kq + 1) * 32 + mr] = av[r].y;
        As[(kq + 2) * 32 + mr] = av[r].z; As[(kq + 3) * 32 + mr] = av[r].w;
        Bs[(kq + 0) * 32 + mr] = wv[r].x; Bs[(kq + 1) * 32 + mr] = wv[r].y;
        Bs[(kq + 2) * 32 + mr] = wv[r].z; Bs[(kq + 3) * 32 + mr] = wv[r].w;
    }
}

// 32x32 tile of Ap(32xK) @ W(rows n0.., stride Hsz)^T over K=[kbase, kbase+klen).
// Group-partial results land in sm[g*1024 + m*32 + n]; caller sums 4 groups.
__device__ __forceinline__ void tile_accum(const float* __restrict__ Ap,
                                           const float* __restrict__ Wb,
                                           int n0, int kbase, int klen,
                                           int g, int u, int tm, int tn,
                                           float* As, float* Bs, float* sm) {
    float acc[4][4] = {};
    const int kslice = klen >> 2;
    const int kb = kbase + g * kslice;
    float4 a0[2], w0[2], a1[2], w1[2];
    ldg_chunk(Ap, Wb, n0, kb, u, a0, w0);
    for (int kc = 0; kc < kslice; kc += 16) {
        sts_chunk(a0, w0, u, As, Bs);
        __syncthreads();
        if (kc + 16 < kslice) ldg_chunk(Ap, Wb, n0, kb + kc + 16, u, a1, w1);
#pragma unroll
        for (int kk = 0; kk < 16; kk++) {
            float4 a = *(const float4*)(As + kk * 32 + tm);
            float4 b = *(const float4*)(Bs + kk * 32 + tn);
            FMA16();
        }
        __syncthreads();
#pragma unroll
        for (int r = 0; r < 2; r++) { a0[r] = a1[r]; w0[r] = w1[r]; }
    }
#pragma unroll
    for (int i = 0; i < 4; i++) {
        float* d = sm + (g << 10) + (tm + i) * 32 + tn;
        d[0] = acc[i][0]; d[1] = acc[i][1]; d[2] = acc[i][2]; d[3] = acc[i][3];
    }
    __syncthreads();
}

#define SM4(m, n) (sm[(m)*32+(n)] + sm[1024+(m)*32+(n)] + sm[2048+(m)*32+(n)] + sm[3072+(m)*32+(n)])

// ---------------- persistent recurrence kernel ----------------
__global__ __launch_bounds__(256, 1) void k_recur(const float* __restrict__ Wx,
                                                  const float* __restrict__ Wh,
                                                  const float* __restrict__ bxp) {
    __shared__ __align__(16) float sm[4096];
    __shared__ int s_win;
    const int tid = threadIdx.x;
    const int b = blockIdx.x;
    const int g = tid >> 6;
    const int u = tid & 63;
    float* As = sm + (g << 10);
    float* Bs = As + 512;
    const int tm = (u >> 3) << 2;
    const int tn = (u & 7) << 2;
    unsigned bar = 0;

    for (int t = 0; t < Ssz; t++) {
        const float* xp = g_xp0 + (size_t)t * Bsz * 3072;

        // ---- Phase A: L0 z,r gates + L1 raw Wh z,r projections (128 tasks) ----
        if (b < 128) {
            const int sel = b >> 5;            // 0:z0 1:r0 2:pz1 3:pr1
            const int n0 = (b & 31) << 5;
            const float* Ap = (sel < 2) ? g_h0 : g_h1;
            const int widx = (sel == 0) ? 0 : (sel == 1) ? 1 : (sel == 2) ? 3 : 4;
            tile_accum(Ap, Wh + (size_t)widx * 1048576, n0, 0, 1024, g, u, tm, tn, As, Bs, sm);
#pragma unroll
            for (int jj = 0; jj < 4; jj++) {
                int o = tid + (jj << 8);
                int m = o >> 5, n = o & 31;
                float v = SM4(m, n);
                int i = n0 + n;
                if (sel == 0)      g_z0[m * Hsz + i] = sigf(v + xp[m * 3072 + i]);
                else if (sel == 1) g_rh0[m * Hsz + i] = sigf(v + xp[m * 3072 + 1024 + i]) * g_h0[m * Hsz + i];
                else if (sel == 2) g_pz1[m * Hsz + i] = v;
                else               g_pr1[m * Hsz + i] = v;
            }
        }
        gridbar(++bar);

        // ---- Phase B: L0 candidate, 128 blocks (32 tiles x 4 K-slices),
        //      last-arriver ticket does the fused h0 update ----
        if (b < 128) {
            const int tile = b & 31;
            const int slice = b >> 5;
            const int n0 = tile << 5;
            tile_accum(g_rh0, Wh + (size_t)2 * 1048576, n0, slice << 8, 256, g, u, tm, tn, As, Bs, sm);
#pragma unroll
            for (int jj = 0; jj < 4; jj++) {
                int o = tid + (jj << 8);
                int m = o >> 5, n = o & 31;
                g_partB[(slice << 15) + (m << 10) + n0 + n] = SM4(m, n);
            }
            __syncthreads();
            __threadfence();
            if (tid == 0) s_win = ((atomicAdd(&g_tickB[tile], 1u) & 3u) == 3u) ? 1 : 0;
            __syncthreads();
            if (s_win) {
#pragma unroll
                for (int jj = 0; jj < 4; jj++) {
                    int o = tid + (jj << 8);
                    int m = o >> 5, n = o & 31;
                    int i = n0 + n;
                    int off = (m << 10) + i;
                    float p = __ldcg(&g_partB[off]) + __ldcg(&g_partB[32768 + off])
                            + __ldcg(&g_partB[65536 + off]) + __ldcg(&g_partB[98304 + off])
                            + xp[m * 3072 + 2048 + i];
                    float c = tanhf(p);
                    float z = g_z0[off];
                    float h = g_h0[off];
                    g_h0[off] = z * h + (1.f - z) * c;
                }
            }
        }
        gridbar(++bar);

        // ---- Phase C: L1 x-projections + gate fuse (96 tasks) ----
        if (b < 96) {
            const int gate = b >> 5;
            const int n0 = (b & 31) << 5;
            tile_accum(g_h0, Wx + (size_t)(3 + gate) * 1048576, n0, 0, 1024, g, u, tm, tn, As, Bs, sm);
#pragma unroll
            for (int jj = 0; jj < 4; jj++) {
                int o = tid + (jj << 8);
                int m = o >> 5, n = o & 31;
                float v = SM4(m, n);
                int i = n0 + n;
                float val = v + bxp[3072 + (gate << 10) + i];
                if (gate == 0)      g_z1[m * Hsz + i] = sigf(val + g_pz1[m * Hsz + i]);
                else if (gate == 1) g_rh1[m * Hsz + i] = sigf(val + g_pr1[m * Hsz + i]) * g_h1[m * Hsz + i];
                else                g_gc1[m * Hsz + i] = val;
            }
        }
        gridbar(++bar);

        // ---- Phase D: L1 candidate, 128 blocks, ticket does h1 update + store ----
        if (b < 128) {
            const int tile = b & 31;
            const int slice = b >> 5;
            const int n0 = tile << 5;
            tile_accum(g_rh1, Wh + (size_t)5 * 1048576, n0, slice << 8, 256, g, u, tm, tn, As, Bs, sm);
#pragma unroll
            for (int jj = 0; jj < 4; jj++) {
                int o = tid + (jj << 8);
                int m = o >> 5, n = o & 31;
                g_partD[(slice << 15) + (m << 10) + n0 + n] = SM4(m, n);
            }
            __syncthreads();
            __threadfence();
            if (tid == 0) s_win = ((atomicAdd(&g_tickD[tile], 1u) & 3u) == 3u) ? 1 : 0;
            __syncthreads();
            if (s_win) {
#pragma unroll
                for (int jj = 0; jj < 4; jj++) {
                    int o = tid + (jj << 8);
                    int m = o >> 5, n = o & 31;
                    int i = n0 + n;
                    int off = (m << 10) + i;
                    float p = __ldcg(&g_partD[off]) + __ldcg(&g_partD[32768 + off])
                            + __ldcg(&g_partD[65536 + off]) + __ldcg(&g_partD[98304 + off])
                            + g_gc1[off];
                    float c = tanhf(p);
                    float z = g_z1[off];
                    float h = g_h1[off];
                    float hn = z * h + (1.f - z) * c;
                    g_h1[off] = hn;
                    g_h1all[(size_t)t * Bsz * Hsz + off] = hn;
                }
            }
        }
        gridbar(++bar);
    }
}

// ---- final hidden state (B,L,H) appended after layer_output ----
__global__ void k_hid(float* __restrict__ out) {
    int idx = blockIdx.x * blockDim.x + threadIdx.x;
    int b = idx >> 11;
    int r = idx & 2047;
    int l = r >> 10;
    int i = r & 1023;
    out[(size_t)Bsz * Ssz * Osz + idx] = (l == 0 ? g_h0 : g_h1)[b * Hsz + i];
}

// ---------------- launch (5 graph nodes) ----------------
extern "C" void kernel_launch(void* const* d_in, const int* in_sizes, int n_in,
                              void* d_out, int out_size) {
    const float* x   = (const float*)d_in[0];
    const float* h0  = (const float*)d_in[1];
    const float* Wx  = (const float*)d_in[2];
    const float* Wh  = (const float*)d_in[3];
    const float* bx  = (const float*)d_in[4];
    const float* Wo  = (const float*)d_in[5];
    const float* bo  = (const float*)d_in[6];
    float* out = (float*)d_out;

    k_init<<<64, 1024>>>(h0);
    k_xproj<<<dim3(48, 256), 256>>>(x, Wx, bx);
    k_recur<<<GRID, 256>>>(Wx, Wh, bx);
    k_out<<<dim3(16, 256), 256>>>(Wo, bo, out);
    k_hid<<<64, 1024>>>(out);
}

// round 9
// speedup vs baseline: 1.3940x; 1.0253x over previous
#include <cuda_runtime.h>
#include <math.h>

#define Bsz 32
#define Ssz 512
#define Hsz 1024
#define Osz 1024
#define GRID 148

// ---------------- device scratch ----------------
__device__ float g_xp0[(size_t)Ssz * Bsz * 3 * Hsz];   // layer0 x-projections (s,b,3H)
__device__ float g_h1all[(size_t)Ssz * Bsz * Hsz];     // all layer1 hidden states (s,b,H)
__device__ float g_h0[Bsz * Hsz];
__device__ float g_h1[Bsz * Hsz];
__device__ float g_z0[Bsz * Hsz];
__device__ float g_rh0[Bsz * Hsz];
__device__ float g_z1[Bsz * Hsz];
__device__ float g_rh1[Bsz * Hsz];
__device__ float g_gc1[Bsz * Hsz];
__device__ float g_pz1[Bsz * Hsz];           // raw h1 @ Wh[1][0]^T
__device__ float g_pr1[Bsz * Hsz];           // raw h1 @ Wh[1][1]^T
__device__ float g_partB[4 * Bsz * Hsz];     // K-split partials, layer0 candidate
__device__ float g_partD[4 * Bsz * Hsz];     // K-split partials, layer1 candidate
__device__ unsigned g_tickB[32];             // per-tile tickets (monotonic)
__device__ unsigned g_tickD[32];
__device__ unsigned g_barcnt;

__device__ __forceinline__ float sigf(float x) { return 1.f / (1.f + expf(-x)); }

#define FMA16() do { \
    acc[0][0] += a.x*b.x; acc[0][1] += a.x*b.y; acc[0][2] += a.x*b.z; acc[0][3] += a.x*b.w; \
    acc[1][0] += a.y*b.x; acc[1][1] += a.y*b.y; acc[1][2] += a.y*b.z; acc[1][3] += a.y*b.w; \
    acc[2][0] += a.z*b.x; acc[2][1] += a.z*b.y; acc[2][2] += a.z*b.z; acc[2][3] += a.z*b.w; \
    acc[3][0] += a.w*b.x; acc[3][1] += a.w*b.y; acc[3][2] += a.w*b.z; acc[3][3] += a.w*b.w; \
} while (0)

// ---------------- grid barrier (monotonic counter) ----------------
__device__ __forceinline__ void gridbar(unsigned gen) {
    __syncthreads();
    __threadfence();
    if (threadIdx.x == 0) {
        atomicAdd(&g_barcnt, 1u);
        const unsigned tgt = gen * GRID;
        while (*(volatile unsigned*)&g_barcnt < tgt) { }
    }
    __syncthreads();
    __threadfence();
}

// ---------------- init ----------------
__global__ void k_init(const float* __restrict__ h0in) {
    if (blockIdx.x == 0 && threadIdx.x == 0) g_barcnt = 0u;
    int idx = blockIdx.x * blockDim.x + threadIdx.x;
    int b = idx >> 11;
    int r = idx & 2047;
    int l = r >> 10;
    int i = r & 1023;
    float v = h0in[idx];
    if (l == 0) g_h0[b * Hsz + i] = v;
    else        g_h1[b * Hsz + i] = v;
}

// ---------------- big GEMM: xp0 = x @ Wx[0]^T + bx[0] (double-buffered) ----------------
__global__ __launch_bounds__(256) void k_xproj(const float* __restrict__ x,
                                               const float* __restrict__ Wx,
                                               const float* __restrict__ bxp) {
    __shared__ __align__(16) float stage[4096];   // 2 bufs x (As 1024 + Bs 1024)
    const int tid = threadIdx.x;
    const int bm = blockIdx.y << 6;
    const int bn = blockIdx.x << 6;
    const int lr = tid >> 2;
    const int lk = (tid & 3) << 2;
    const int mrow = bm + lr;
    const size_t a_off = ((size_t)(mrow & 31) * Ssz + (mrow >> 5)) * Hsz;
    const size_t b_off = (size_t)(bn + lr) * Hsz;
    const int tm = (tid >> 4) << 2;
    const int tn = (tid & 15) << 2;
    float acc[4][4] = {};
    float4 av = *(const float4*)(x + a_off + lk);
    float4 bv = __ldcg((const float4*)(Wx + b_off + lk));
    for (int k0 = 0; k0 < Hsz; k0 += 16) {
        float* As = stage + (((k0 >> 4) & 1) << 11);
        float* Bs = As + 1024;
        As[(lk + 0) * 64 + lr] = av.x; As[(lk + 1) * 64 + lr] = av.y;
        As[(lk + 2) * 64 + lr] = av.z; As[(lk + 3) * 64 + lr] = av.w;
        Bs[(lk + 0) * 64 + lr] = bv.x; Bs[(lk + 1) * 64 + lr] = bv.y;
        Bs[(lk + 2) * 64 + lr] = bv.z; Bs[(lk + 3) * 64 + lr] = bv.w;
        __syncthreads();
        if (k0 + 16 < Hsz) {
            av = *(const float4*)(x + a_off + k0 + 16 + lk);
            bv = __ldcg((const float4*)(Wx + b_off + k0 + 16 + lk));
        }
#pragma unroll
        for (int kk = 0; kk < 16; kk++) {
            float4 a = *(const float4*)(As + kk * 64 + tm);
            float4 b = *(const float4*)(Bs + kk * 64 + tn);
            FMA16();
        }
    }
#pragma unroll
    for (int i = 0; i < 4; i++) {
        size_t ro = (size_t)(bm + tm + i) * 3072;
#pragma unroll
        for (int j = 0; j < 4; j++) {
            int n = bn + tn + j;
            g_xp0[ro + n] = acc[i][j] + bxp[n];
        }
    }
}

// ---------------- big GEMM: out = h1all @ Wo^T + bo (double-buffered) ----------------
__global__ __launch_bounds__(256) void k_out(const float* __restrict__ Wo,
                                             const float* __restrict__ bo,
                                             float* __restrict__ out) {
    __shared__ __align__(16) float stage[4096];
    const int tid = threadIdx.x;
    const int bm = blockIdx.y << 6;
    const int bn = blockIdx.x << 6;
    const int lr = tid >> 2;
    const int lk = (tid & 3) << 2;
    const size_t a_off = (size_t)(bm + lr) * Hsz;
    const size_t b_off = (size_t)(bn + lr) * Hsz;
    const int tm = (tid >> 4) << 2;
    const int tn = (tid & 15) << 2;
    float acc[4][4] = {};
    float4 av = *(const float4*)(g_h1all + a_off + lk);
    float4 bv = __ldcg((const float4*)(Wo + b_off + lk));
    for (int k0 = 0; k0 < Hsz; k0 += 16) {
        float* As = stage + (((k0 >> 4) & 1) << 11);
        float* Bs = As + 1024;
        As[(lk + 0) * 64 + lr] = av.x; As[(lk + 1) * 64 + lr] = av.y;
        As[(lk + 2) * 64 + lr] = av.z; As[(lk + 3) * 64 + lr] = av.w;
        Bs[(lk + 0) * 64 + lr] = bv.x; Bs[(lk + 1) * 64 + lr] = bv.y;
        Bs[(lk + 2) * 64 + lr] = bv.z; Bs[(lk + 3) * 64 + lr] = bv.w;
        __syncthreads();
        if (k0 + 16 < Hsz) {
            av = *(const float4*)(g_h1all + a_off + k0 + 16 + lk);
            bv = __ldcg((const float4*)(Wo + b_off + k0 + 16 + lk));
        }
#pragma unroll
        for (int kk = 0; kk < 16; kk++) {
            float4 a = *(const float4*)(As + kk * 64 + tm);
            float4 b = *(const float4*)(Bs + kk * 64 + tn);
            FMA16();
        }
    }
#pragma unroll
    for (int i = 0; i < 4; i++) {
        int m = bm + tm + i;
        int bb = m & 31;
        int s = m >> 5;
        size_t ro = ((size_t)bb * Ssz + s) * Osz;
#pragma unroll
        for (int j = 0; j < 4; j++) {
            int n = bn + tn + j;
            out[ro + n] = acc[i][j] + bo[n];
        }
    }
}

// ---------------- 32x32 tile GEMM (4-way K-split, double-buffered) ----------------
__device__ __forceinline__ void ldg_chunk(const float* __restrict__ Ap,
                                          const float* __restrict__ Wb,
                                          int n0, int kk0, int u,
                                          float4 av[2], float4 wv[2]) {
#pragma unroll
    for (int r = 0; r < 2; r++) {
        int p = u + (r << 6);
        int mr = p >> 2;
        int kq = (p & 3) << 2;
        av[r] = *(const float4*)(Ap + mr * Hsz + kk0 + kq);
        wv[r] = __ldcg((const float4*)(Wb + (size_t)(n0 + mr) * Hsz + kk0 + kq));
    }
}

__device__ __forceinline__ void sts_chunk(const float4 av[2], const float4 wv[2],
                                          int u, float* As, float* Bs) {
#pragma unroll
    for (int r = 0; r < 2; r++) {
        int p = u + (r << 6);
        int mr = p >> 2;
        int kq = (p & 3) << 2;
        As[(kq + 0) * 32 + mr] = av[r].x; As[(kq + 1) * 32 + mr] = av[r].y;
        As[(kq + 2) * 32 + mr] = av[r].z; As[(kq + 3) * 32 + mr] = av[r].w;
        Bs[(kq + 0) * 32 + mr] = wv[r].x; Bs[(kq + 1) * 32 + mr] = wv[r].y;
        Bs[(kq + 2) * 32 + mr] = wv[r].z; Bs[(kq + 3) * 32 + mr] = wv[r].w;
    }
}

// 32x32 tile of Ap(32xK) @ W(rows n0.., stride Hsz)^T over K=[kbase, kbase+klen).
// Group partials land in sm_all[g*1024 + m*32 + n] (aliases group 0/1 staging;
// guarded by syncthreads). Caller sums 4 groups via SM4.
__device__ __forceinline__ void tile_accum(const float* __restrict__ Ap,
                                           const float* __restrict__ Wb,
                                           int n0, int kbase, int klen,
                                           int g, int u, int tm, int tn,
                                           float* sm_all) {
    float acc[4][4] = {};
    float* stage = sm_all + (g << 11);   // 2 bufs x (As 512 + Bs 512)
    const int kslice = klen >> 2;
    const int kb = kbase + g * kslice;
    float4 a0[2], w0[2];
    ldg_chunk(Ap, Wb, n0, kb, u, a0, w0);
    for (int kc = 0; kc < kslice; kc += 16) {
        float* As = stage + (((kc >> 4) & 1) << 10);
        float* Bs = As + 512;
        sts_chunk(a0, w0, u, As, Bs);
        __syncthreads();
        if (kc + 16 < kslice) ldg_chunk(Ap, Wb, n0, kb + kc + 16, u, a0, w0);
#pragma unroll
        for (int kk = 0; kk < 16; kk++) {
            float4 a = *(const float4*)(As + kk * 32 + tm);
            float4 b = *(const float4*)(Bs + kk * 32 + tn);
            FMA16();
        }
    }
    __syncthreads();   // staging reads done before partials overwrite the alias
#pragma unroll
    for (int i = 0; i < 4; i++) {
        float* d = sm_all + (g << 10) + (tm + i) * 32 + tn;
        d[0] = acc[i][0]; d[1] = acc[i][1]; d[2] = acc[i][2]; d[3] = acc[i][3];
    }
    __syncthreads();
}

#define SM4(m, n) (sm[(m)*32+(n)] + sm[1024+(m)*32+(n)] + sm[2048+(m)*32+(n)] + sm[3072+(m)*32+(n)])

// ---------------- persistent recurrence kernel ----------------
__global__ __launch_bounds__(256, 1) void k_recur(const float* __restrict__ Wx,
                                                  const float* __restrict__ Wh,
                                                  const float* __restrict__ bxp) {
    __shared__ __align__(16) float sm[8192];   // staging (32KB) / partials alias
    __shared__ int s_win;
    const int tid = threadIdx.x;
    const int b = blockIdx.x;
    const int g = tid >> 6;
    const int u = tid & 63;
    const int tm = (u >> 3) << 2;
    const int tn = (u & 7) << 2;
    unsigned bar = 0;

    for (int t = 0; t < Ssz; t++) {
        const float* xp = g_xp0 + (size_t)t * Bsz * 3072;

        // ---- Phase A: L0 z,r gates + L1 raw Wh z,r projections (128 tasks) ----
        if (b < 128) {
            const int sel = b >> 5;            // 0:z0 1:r0 2:pz1 3:pr1
            const int n0 = (b & 31) << 5;
            const float* Ap = (sel < 2) ? g_h0 : g_h1;
            const int widx = (sel == 0) ? 0 : (sel == 1) ? 1 : (sel == 2) ? 3 : 4;
            tile_accum(Ap, Wh + (size_t)widx * 1048576, n0, 0, 1024, g, u, tm, tn, sm);
#pragma unroll
            for (int jj = 0; jj < 4; jj++) {
                int o = tid + (jj << 8);
                int m = o >> 5, n = o & 31;
                float v = SM4(m, n);
                int i = n0 + n;
                if (sel == 0)      g_z0[m * Hsz + i] = sigf(v + xp[m * 3072 + i]);
                else if (sel == 1) g_rh0[m * Hsz + i] = sigf(v + xp[m * 3072 + 1024 + i]) * g_h0[m * Hsz + i];
                else if (sel == 2) g_pz1[m * Hsz + i] = v;
                else               g_pr1[m * Hsz + i] = v;
            }
        }
        gridbar(++bar);

        // ---- Phase B: L0 candidate, 128 blocks (32 tiles x 4 K-slices),
        //      last-arriver ticket does the fused h0 update ----
        if (b < 128) {
            const int tile = b & 31;
            const int slice = b >> 5;
            const int n0 = tile << 5;
            tile_accum(g_rh0, Wh + (size_t)2 * 1048576, n0, slice << 8, 256, g, u, tm, tn, sm);
#pragma unroll
            for (int jj = 0; jj < 4; jj++) {
                int o = tid + (jj << 8);
                int m = o >> 5, n = o & 31;
                g_partB[(slice << 15) + (m << 10) + n0 + n] = SM4(m, n);
            }
            __syncthreads();
            __threadfence();
            if (tid == 0) s_win = ((atomicAdd(&g_tickB[tile], 1u) & 3u) == 3u) ? 1 : 0;
            __syncthreads();
            if (s_win) {
#pragma unroll
                for (int jj = 0; jj < 4; jj++) {
                    int o = tid + (jj << 8);
                    int m = o >> 5, n = o & 31;
                    int i = n0 + n;
                    int off = (m << 10) + i;
                    float p = __ldcg(&g_partB[off]) + __ldcg(&g_partB[32768 + off])
                            + __ldcg(&g_partB[65536 + off]) + __ldcg(&g_partB[98304 + off])
                            + xp[m * 3072 + 2048 + i];
                    float c = tanhf(p);
                    float z = g_z0[off];
                    float h = g_h0[off];
                    g_h0[off] = z * h + (1.f - z) * c;
                }
            }
        }
        gridbar(++bar);

        // ---- Phase C: L1 x-projections + gate fuse (96 tasks) ----
        if (b < 96) {
            const int gate = b >> 5;
            const int n0 = (b & 31) << 5;
            tile_accum(g_h0, Wx + (size_t)(3 + gate) * 1048576, n0, 0, 1024, g, u, tm, tn, sm);
#pragma unroll
            for (int jj = 0; jj < 4; jj++) {
                int o = tid + (jj << 8);
                int m = o >> 5, n = o & 31;
                float v = SM4(m, n);
                int i = n0 + n;
                float val = v + bxp[3072 + (gate << 10) + i];
                if (gate == 0)      g_z1[m * Hsz + i] = sigf(val + g_pz1[m * Hsz + i]);
                else if (gate == 1) g_rh1[m * Hsz + i] = sigf(val + g_pr1[m * Hsz + i]) * g_h1[m * Hsz + i];
                else                g_gc1[m * Hsz + i] = val;
            }
        }
        gridbar(++bar);

        // ---- Phase D: L1 candidate, 128 blocks, ticket does h1 update + store ----
        if (b < 128) {
            const int tile = b & 31;
            const int slice = b >> 5;
            const int n0 = tile << 5;
            tile_accum(g_rh1, Wh + (size_t)5 * 1048576, n0, slice << 8, 256, g, u, tm, tn, sm);
#pragma unroll
            for (int jj = 0; jj < 4; jj++) {
                int o = tid + (jj << 8);
                int m = o >> 5, n = o & 31;
                g_partD[(slice << 15) + (m << 10) + n0 + n] = SM4(m, n);
            }
            __syncthreads();
            __threadfence();
            if (tid == 0) s_win = ((atomicAdd(&g_tickD[tile], 1u) & 3u) == 3u) ? 1 : 0;
            __syncthreads();
            if (s_win) {
#pragma unroll
                for (int jj = 0; jj < 4; jj++) {
                    int o = tid + (jj << 8);
                    int m = o >> 5, n = o & 31;
                    int i = n0 + n;
                    int off = (m << 10) + i;
                    float p = __ldcg(&g_partD[off]) + __ldcg(&g_partD[32768 + off])
                            + __ldcg(&g_partD[65536 + off]) + __ldcg(&g_partD[98304 + off])
                            + g_gc1[off];
                    float c = tanhf(p);
                    float z = g_z1[off];
                    float h = g_h1[off];
                    float hn = z * h + (1.f - z) * c;
                    g_h1[off] = hn;
                    g_h1all[(size_t)t * Bsz * Hsz + off] = hn;
                }
            }
        }
        gridbar(++bar);
    }
}

// ---- final hidden state (B,L,H) appended after layer_output ----
__global__ void k_hid(float* __restrict__ out) {
    int idx = blockIdx.x * blockDim.x + threadIdx.x;
    int b = idx >> 11;
    int r = idx & 2047;
    int l = r >> 10;
    int i = r & 1023;
    out[(size_t)Bsz * Ssz * Osz + idx] = (l == 0 ? g_h0 : g_h1)[b * Hsz + i];
}

// ---------------- launch (5 graph nodes) ----------------
extern "C" void kernel_launch(void* const* d_in, const int* in_sizes, int n_in,
                              void* d_out, int out_size) {
    const float* x   = (const float*)d_in[0];
    const float* h0  = (const float*)d_in[1];
    const float* Wx  = (const float*)d_in[2];
    const float* Wh  = (const float*)d_in[3];
    const float* bx  = (const float*)d_in[4];
    const float* Wo  = (const float*)d_in[5];
    const float* bo  = (const float*)d_in[6];
    float* out = (float*)d_out;

    k_init<<<64, 1024>>>(h0);
    k_xproj<<<dim3(48, 256), 256>>>(x, Wx, bx);
    k_recur<<<GRID, 256>>>(Wx, Wh, bx);
    k_out<<<dim3(16, 256), 256>>>(Wo, bo, out);
    k_hid<<<64, 1024>>>(out);
}